// round 13
// baseline (speedup 1.0000x reference)
#include <cuda_runtime.h>
#include <cstdint>

#define R 4096
#define F 256
#define K 8
#define CMIN 1e-6f
#define CMAX 1e6f
#define C_BIAS 0.5287663729448977f  /* log2(log2(e)) */
#define INV254 0.003937007874015748f

#define BM 128
#define BN 64
#define TILE_A 16384               // 128 rows x 128B int8 (K-chunk = 128)
#define TILE_Bb 8192               // 64 rows x 128B int8
#define A_SMEM (2 * TILE_A + 2 * TILE_Bb + 1024)

// Scratch (static device globals — no runtime allocation)
__device__ __align__(16) float g_base[(size_t)R * (size_t)R];  // 64 MB
__device__ __align__(16) float g_S[K * R];
__device__ __align__(16) float g_rs[4 * R];     // sx1 | n2x1 | sx2 | n2x2
__device__ __align__(16) float g_sc[2 * R];     // row scales: x1 | x2
__device__ __align__(16) float g_kc[5 * K];     // compacted: akt|bkt2|ekc2|hi|nw
__device__ int g_nact;
__device__ __align__(16) int8_t g_x1h[R * F];
__device__ __align__(16) int8_t g_x1l[R * F];
__device__ __align__(16) int8_t g_x2h[R * F];
__device__ __align__(16) int8_t g_x2l[R * F];

__device__ __forceinline__ uint32_t smem_u32(const void* p) {
    uint32_t a;
    asm("{ .reg .u64 t; cvta.to.shared.u64 t, %1; cvt.u32.u64 %0, t; }"
        : "=r"(a) : "l"(p));
    return a;
}
__device__ __forceinline__ float ex2f(float x) {
    float y;
    asm("ex2.approx.ftz.f32 %0, %1;" : "=f"(y) : "f"(x));
    return y;
}
__device__ __forceinline__ void ldsm_x4(uint32_t* r, uint32_t addr) {
    asm volatile("ldmatrix.sync.aligned.m8n8.x4.shared.b16 {%0,%1,%2,%3}, [%4];"
                 : "=r"(r[0]), "=r"(r[1]), "=r"(r[2]), "=r"(r[3]) : "r"(addr));
}
__device__ __forceinline__ void mma_s8(int* c, const uint32_t* a,
                                       uint32_t b0, uint32_t b1) {
    asm volatile(
        "mma.sync.aligned.m16n8k32.row.col.s32.s8.s8.s32 "
        "{%0,%1,%2,%3}, {%4,%5,%6,%7}, {%8,%9}, {%0,%1,%2,%3};"
        : "+r"(c[0]), "+r"(c[1]), "+r"(c[2]), "+r"(c[3])
        : "r"(a[0]), "r"(a[1]), "r"(a[2]), "r"(a[3]), "r"(b0), "r"(b1));
}

// ---------------------------------------------------------------------------
// Per-k constants, compacted to softmax weights > 1e-7 (others contribute
// < 1e-7 relative). arg = dist*ekc2 + C_BIAS; e^kv = ex2(ex2(arg)).
__global__ void params_kernel(const float* __restrict__ sig,
                              const float* __restrict__ mean,
                              const float* __restrict__ sp) {
    if (threadIdx.x == 0) {
        const float L2E = 1.4426950408889634f;
        float w[K];
        float m = -3.4e38f;
        #pragma unroll
        for (int k = 0; k < K; k++) {
            float v = 1.0f / (sp[k] * sp[k]);
            w[k] = v;
            if (v > m) m = v;
        }
        float s = 0.0f;
        #pragma unroll
        for (int k = 0; k < K; k++) { w[k] = __expf(w[k] - m); s += w[k]; }
        float inv_s = 1.0f / s;
        int na = 0;
        for (int k = 0; k < K; k++) {
            float nw = w[k] * inv_s;
            if (nw > 1e-7f) {
                float ekc2 = -L2E / (2.0f * sig[k] * sig[k]);
                float ak   = -2.0f * mean[k];
                float bk   = (float)F * mean[k] * mean[k];
                g_kc[na]         = ak * ekc2;              // akt
                g_kc[K + na]     = bk * ekc2 + C_BIAS;     // bkt2
                g_kc[2 * K + na] = ekc2;
                g_kc[3 * K + na] = CMIN * ekc2 + C_BIAS;   // hi clamp
                g_kc[4 * K + na] = nw;                     // weight
                na++;
            }
        }
        g_nact = na;
    }
}

// ---------------------------------------------------------------------------
// Fused prep: zero g_S; one warp per row computes maxabs, row sum, sq-norm,
// and the int8 hi/lo fixed-point split: x ~= s*(h + l/254), s = maxabs/127.
__global__ void __launch_bounds__(256)
prep_kernel(const float* __restrict__ x1, const float* __restrict__ x2) {
    const int gid = blockIdx.x * blockDim.x + threadIdx.x;
    if (gid < K * R) g_S[gid] = 0.0f;

    const int w    = gid >> 5;
    const int lane = gid & 31;
    const bool is1 = (w < R);
    const int row  = is1 ? w : (w - R);
    const float* x = is1 ? x1 : x2;
    int8_t* xh = is1 ? g_x1h : g_x2h;
    int8_t* xl = is1 ? g_x1l : g_x2l;

    const float* p = x + (size_t)row * F + lane * 8;
    float4 v0 = *(const float4*)p;
    float4 v1 = *(const float4*)(p + 4);
    float vals[8] = {v0.x, v0.y, v0.z, v0.w, v1.x, v1.y, v1.z, v1.w};

    float s = 0.0f, q = 0.0f, m = 0.0f;
    #pragma unroll
    for (int e = 0; e < 8; e++) {
        float v = vals[e];
        s += v;
        q = fmaf(v, v, q);
        m = fmaxf(m, fabsf(v));
    }
    #pragma unroll
    for (int o = 16; o > 0; o >>= 1) {
        s += __shfl_xor_sync(0xFFFFFFFFu, s, o);
        q += __shfl_xor_sync(0xFFFFFFFFu, q, o);
        m = fmaxf(m, __shfl_xor_sync(0xFFFFFFFFu, m, o));
    }
    m = fmaxf(m, 1e-30f);
    const float inv = 127.0f / m;

    int8_t hb[8], lb[8];
    #pragma unroll
    for (int e = 0; e < 8; e++) {
        float vh = vals[e] * inv;
        int h = __float2int_rn(vh);
        float rem = vh - (float)h;
        int l = __float2int_rn(rem * 254.0f);
        hb[e] = (int8_t)h;
        lb[e] = (int8_t)l;
    }
    *(uint2*)(xh + (size_t)row * F + lane * 8) = *(const uint2*)hb;
    *(uint2*)(xl + (size_t)row * F + lane * 8) = *(const uint2*)lb;

    if (lane == 0) {
        int off = is1 ? 0 : 2 * R;
        g_rs[off + row]     = s;
        g_rs[off + R + row] = q;
        g_sc[(is1 ? 0 : R) + row] = m / 127.0f;
    }
}

// ---------------------------------------------------------------------------
// Kernel A: 128x64 tile, int8 split-GEMM (hh into acc_h; hl+lh into acc_m)
// via mma.sync m16n8k32.s8. 8 warps 2(m) x 4(n), 64x16 per warp.
// Epilogue: base transform (or numerator when nact==1) + S accumulation.
__global__ void __launch_bounds__(256, 2)
kernelA() {
    extern __shared__ char dynsmem[];
    __shared__ float skc[5 * K];
    __shared__ int s_na;

    const int tid  = threadIdx.x;
    const int wid  = tid >> 5;
    const int lane = tid & 31;
    const int wm = wid & 1;          // m position -> 64 rows
    const int wn = wid >> 1;         // n position -> 16 cols
    const int ln15 = lane & 15;
    const int hi16 = lane >> 4;
    const int r0 = blockIdx.y * BM;
    const int c0 = blockIdx.x * BN;

    const uint32_t dsb = smem_u32(dynsmem);
    const uint32_t tiles_u = (dsb + 1023u) & ~1023u;
    char* tiles = dynsmem + (tiles_u - dsb);

    if (tid < 5 * K) skc[tid] = g_kc[tid];
    if (tid == 0) s_na = g_nact;

    // loader mapping: A tiles 128x128B, B tiles 64x128B, SW128 swizzle
    const int arow = tid >> 1, acol = (tid & 1) * 64;
    const int brow = tid >> 2, bcol = (tid & 3) * 32;
    const int8_t* pah = g_x1h + (size_t)(r0 + arow) * F + acol;
    const int8_t* pal = g_x1l + (size_t)(r0 + arow) * F + acol;
    const int8_t* pbh = g_x2h + (size_t)(c0 + brow) * F + bcol;
    const int8_t* pbl = g_x2l + (size_t)(c0 + brow) * F + bcol;

    const uint32_t ah_b = tiles_u + 0 * TILE_A + (uint32_t)(wm * 64 + ln15) * 128u;
    const uint32_t al_b = tiles_u + 1 * TILE_A + (uint32_t)(wm * 64 + ln15) * 128u;
    const uint32_t bh_b = tiles_u + 2 * TILE_A + (uint32_t)(wn * 16 + ln15) * 128u;
    const uint32_t bl_b = tiles_u + 2 * TILE_A + TILE_Bb + (uint32_t)(wn * 16 + ln15) * 128u;

    int acc_h[4][2][4], acc_m[4][2][4];
    #pragma unroll
    for (int i = 0; i < 4; i++)
        #pragma unroll
        for (int j = 0; j < 2; j++)
            #pragma unroll
            for (int c = 0; c < 4; c++) { acc_h[i][j][c] = 0; acc_m[i][j][c] = 0; }

    for (int kc = 0; kc < 2; kc++) {
        const int k0 = kc * 128;
        __syncthreads();
        #pragma unroll
        for (int j = 0; j < 4; j++) {
            uint32_t off = arow * 128 + acol + j * 16;
            uint32_t sw = off ^ ((off >> 3) & 0x70);
            *(uint4*)(tiles + 0 * TILE_A + sw) = *(const uint4*)(pah + k0 + j * 16);
            *(uint4*)(tiles + 1 * TILE_A + sw) = *(const uint4*)(pal + k0 + j * 16);
        }
        #pragma unroll
        for (int j = 0; j < 2; j++) {
            uint32_t off = brow * 128 + bcol + j * 16;
            uint32_t sw = off ^ ((off >> 3) & 0x70);
            *(uint4*)(tiles + 2 * TILE_A + sw) = *(const uint4*)(pbh + k0 + j * 16);
            *(uint4*)(tiles + 2 * TILE_A + TILE_Bb + sw) = *(const uint4*)(pbl + k0 + j * 16);
        }
        __syncthreads();

        #pragma unroll
        for (int ks = 0; ks < 4; ks++) {
            const uint32_t q = (uint32_t)(((ks * 2 + hi16) ^ (ln15 & 7)) * 16);
            uint32_t ah[4][4], bh[4], bl[4];
            #pragma unroll
            for (int mf = 0; mf < 4; mf++)
                ldsm_x4(ah[mf], ah_b + q + mf * 2048);
            ldsm_x4(bh, bh_b + q);
            ldsm_x4(bl, bl_b + q);

            // hh -> acc_h
            #pragma unroll
            for (int mf = 0; mf < 4; mf++)
                #pragma unroll
                for (int nf = 0; nf < 2; nf++)
                    mma_s8(acc_h[mf][nf], ah[mf], bh[nf], bh[nf + 2]);
            // hl -> acc_m
            #pragma unroll
            for (int mf = 0; mf < 4; mf++)
                #pragma unroll
                for (int nf = 0; nf < 2; nf++)
                    mma_s8(acc_m[mf][nf], ah[mf], bl[nf], bl[nf + 2]);
            // lh -> acc_m (A-lo overwrites A-hi registers)
            #pragma unroll
            for (int mf = 0; mf < 4; mf++)
                ldsm_x4(ah[mf], al_b + q + mf * 2048);
            #pragma unroll
            for (int mf = 0; mf < 4; mf++)
                #pragma unroll
                for (int nf = 0; nf < 2; nf++)
                    mma_s8(acc_m[mf][nf], ah[mf], bh[nf], bh[nf + 2]);
        }
    }

    // ---- epilogue ----
    // elem (mf, nf, half, e): row = r0 + wm*64 + mf*16 + half*8 + lane/4
    //                         col = c0 + wn*16 + nf*8 + (lane&3)*2 + e
    const int rbase = r0 + wm * 64 + (lane >> 2);
    const int cbase = c0 + wn * 16 + (lane & 3) * 2;

    float sx1r8[8], n21r8[8], sc1r8[8];
    #pragma unroll
    for (int i = 0; i < 8; i++) {
        int row = rbase + (i >> 1) * 16 + (i & 1) * 8;
        sx1r8[i] = g_rs[row];
        n21r8[i] = g_rs[R + row];
        sc1r8[i] = 2.0f * g_sc[row];
    }
    float n22c[4], s2c[4], sc2c[4];
    #pragma unroll
    for (int nf = 0; nf < 2; nf++) {
        float2 n2 = *(const float2*)&g_rs[3 * R + cbase + nf * 8];
        float2 s2 = *(const float2*)&g_rs[2 * R + cbase + nf * 8];
        float2 c2 = *(const float2*)&g_sc[R + cbase + nf * 8];
        n22c[nf * 2] = n2.x; n22c[nf * 2 + 1] = n2.y;
        s2c[nf * 2]  = s2.x; s2c[nf * 2 + 1]  = s2.y;
        sc2c[nf * 2] = c2.x; sc2c[nf * 2 + 1] = c2.y;
    }

    // base = n21 + n22 - 2*s1*s2*(hh + (hl+lh)/254)
    float bacc[4][2][4];
    #pragma unroll
    for (int mf = 0; mf < 4; mf++)
        #pragma unroll
        for (int h = 0; h < 2; h++) {
            float n21 = n21r8[mf * 2 + h];
            float sc1 = sc1r8[mf * 2 + h];
            #pragma unroll
            for (int nf = 0; nf < 2; nf++)
                #pragma unroll
                for (int e = 0; e < 2; e++) {
                    int idx = h * 2 + e;
                    float hf = (float)acc_h[mf][nf][idx];
                    float mf2 = (float)acc_m[mf][nf][idx];
                    float dot = fmaf(mf2, INV254, hf) * (sc1 * sc2c[nf * 2 + e]);
                    bacc[mf][nf][idx] = n21 + n22c[nf * 2 + e] - dot;
                }
        }

    const int na = s_na;
    if (na == 1) {
        // store numerator e^kv directly; kernelB becomes a row-scale pass
        const float akt  = skc[0];
        const float nakt = -akt;
        const float bkt2 = skc[K];
        const float ekc2 = skc[2 * K];
        const float hi   = skc[3 * K];
        #pragma unroll
        for (int mf = 0; mf < 4; mf++)
            #pragma unroll
            for (int h = 0; h < 2; h++) {
                const float pi = fmaf(sx1r8[mf * 2 + h], akt, bkt2);
                float s = 0.0f;
                #pragma unroll
                for (int nf = 0; nf < 2; nf++)
                    #pragma unroll
                    for (int e = 0; e < 2; e++) {
                        int idx = h * 2 + e;
                        float arg = fmaf(bacc[mf][nf][idx], ekc2,
                                         fmaf(s2c[nf * 2 + e], nakt, pi));
                        arg = fminf(arg, hi);
                        float kv = ex2f(ex2f(arg));
                        bacc[mf][nf][idx] = kv;
                        s += kv;
                    }
                int row = rbase + mf * 16 + h * 8;
                #pragma unroll
                for (int nf = 0; nf < 2; nf++) {
                    float2 o = {bacc[mf][nf][h * 2], bacc[mf][nf][h * 2 + 1]};
                    *(float2*)&g_base[(size_t)row * R + cbase + nf * 8] = o;
                }
                s += __shfl_xor_sync(0xFFFFFFFFu, s, 1);
                s += __shfl_xor_sync(0xFFFFFFFFu, s, 2);
                if ((lane & 3) == 0)
                    atomicAdd(&g_S[row], s);
            }
    } else {
        #pragma unroll
        for (int mf = 0; mf < 4; mf++)
            #pragma unroll
            for (int h = 0; h < 2; h++) {
                int row = rbase + mf * 16 + h * 8;
                #pragma unroll
                for (int nf = 0; nf < 2; nf++) {
                    float2 o = {bacc[mf][nf][h * 2], bacc[mf][nf][h * 2 + 1]};
                    *(float2*)&g_base[(size_t)row * R + cbase + nf * 8] = o;
                }
            }
        for (int kk = 0; kk < na; kk++) {
            const float akt  = skc[kk];
            const float nakt = -akt;
            const float bkt2 = skc[K + kk];
            const float ekc2 = skc[2 * K + kk];
            const float hi   = skc[3 * K + kk];
            #pragma unroll
            for (int mf = 0; mf < 4; mf++)
                #pragma unroll
                for (int h = 0; h < 2; h++) {
                    const float pi = fmaf(sx1r8[mf * 2 + h], akt, bkt2);
                    float s = 0.0f;
                    #pragma unroll
                    for (int nf = 0; nf < 2; nf++)
                        #pragma unroll
                        for (int e = 0; e < 2; e++) {
                            float arg = fmaf(bacc[mf][nf][h * 2 + e], ekc2,
                                             fmaf(s2c[nf * 2 + e], nakt, pi));
                            arg = fminf(arg, hi);
                            s += ex2f(ex2f(arg));
                        }
                    s += __shfl_xor_sync(0xFFFFFFFFu, s, 1);
                    s += __shfl_xor_sync(0xFFFFFFFFu, s, 2);
                    if ((lane & 3) == 0)
                        atomicAdd(&g_S[kk * R + rbase + mf * 16 + h * 8], s);
                }
        }
    }
}

// ---------------------------------------------------------------------------
// Kernel B: two rows per block. nact==1: pure row-scale of stored numerators.
// Otherwise recompute numerators from stored base (double-ex2 on MUFU).
__global__ void __launch_bounds__(256)
kernelB(float* __restrict__ out) {
    const int r0 = blockIdx.x * 2;
    __shared__ float sa[K], se[K], shi[K];
    __shared__ float sw0[K], sw1[K], sp0[K], sp1[K];
    __shared__ int s_na;
    if (threadIdx.x == 0) s_na = g_nact;
    if (threadIdx.x < K) {
        int k = threadIdx.x;
        float akt = g_kc[k];
        float nw  = g_kc[4 * K + k];
        float bkt2 = g_kc[K + k];
        sa[k]  = akt;
        se[k]  = g_kc[2 * K + k];
        shi[k] = g_kc[3 * K + k];
        sw0[k] = nw / g_S[k * R + r0];
        sw1[k] = nw / g_S[k * R + r0 + 1];
        sp0[k] = fmaf(g_rs[r0],     akt, bkt2);
        sp1[k] = fmaf(g_rs[r0 + 1], akt, bkt2);
    }
    __syncthreads();

    const int na = s_na;
    const float* brow0 = g_base + (size_t)r0 * R;
    const float* brow1 = g_base + (size_t)(r0 + 1) * R;
    float* orow0 = out + (size_t)r0 * R;
    float* orow1 = out + (size_t)(r0 + 1) * R;

    if (na == 1) {
        const float w0 = sw0[0], w1 = sw1[0];
        #pragma unroll
        for (int it = 0; it < R / (256 * 4); it++) {
            int c = (it * 256 + threadIdx.x) * 4;
            float4 b0 = *(const float4*)(brow0 + c);
            float4 b1 = *(const float4*)(brow1 + c);
            float4 o0 = {b0.x * w0, b0.y * w0, b0.z * w0, b0.w * w0};
            float4 o1 = {b1.x * w1, b1.y * w1, b1.z * w1, b1.w * w1};
            *(float4*)(orow0 + c) = o0;
            *(float4*)(orow1 + c) = o1;
        }
        return;
    }

    #pragma unroll
    for (int it = 0; it < R / (256 * 4); it++) {
        int c = (it * 256 + threadIdx.x) * 4;
        float4 s4  = *(const float4*)(g_rs + 2 * R + c);
        float4 b40 = *(const float4*)(brow0 + c);
        float4 b41 = *(const float4*)(brow1 + c);
        const float* cc  = (const float*)&s4;
        const float* bb0 = (const float*)&b40;
        const float* bb1 = (const float*)&b41;
        float o0[4] = {0.0f, 0.0f, 0.0f, 0.0f};
        float o1[4] = {0.0f, 0.0f, 0.0f, 0.0f};
        for (int kk = 0; kk < na; kk++) {
            const float nakt = -sa[kk];
            const float ekc2 = se[kk];
            const float hi   = shi[kk];
            const float wk0  = sw0[kk];
            const float wk1  = sw1[kk];
            const float pr0  = sp0[kk];
            const float pr1  = sp1[kk];
            #pragma unroll
            for (int j = 0; j < 4; j++) {
                float t = cc[j] * nakt;
                float a0 = fmaf(bb0[j], ekc2, t + pr0);
                float a1 = fmaf(bb1[j], ekc2, t + pr1);
                a0 = fminf(a0, hi);
                a1 = fminf(a1, hi);
                o0[j] = fmaf(ex2f(ex2f(a0)), wk0, o0[j]);
                o1[j] = fmaf(ex2f(ex2f(a1)), wk1, o1[j]);
            }
        }
        float4 ov0 = {o0[0], o0[1], o0[2], o0[3]};
        float4 ov1 = {o1[0], o1[1], o1[2], o1[3]};
        *(float4*)(orow0 + c) = ov0;
        *(float4*)(orow1 + c) = ov1;
    }
}

// ---------------------------------------------------------------------------
extern "C" void kernel_launch(void* const* d_in, const int* in_sizes, int n_in,
                              void* d_out, int out_size) {
    const float* x1   = (const float*)d_in[0];  // [R, F]
    const float* x2   = (const float*)d_in[1];  // [R, F]
    const float* sig  = (const float*)d_in[2];  // [K]
    const float* mean = (const float*)d_in[3];  // [K]
    const float* sp   = (const float*)d_in[4];  // [K]
    float* out = (float*)d_out;                 // [R, R]

    cudaFuncSetAttribute(kernelA, cudaFuncAttributeMaxDynamicSharedMemorySize,
                         A_SMEM);

    params_kernel<<<1, 32>>>(sig, mean, sp);
    prep_kernel<<<(2 * R) / 8, 256>>>(x1, x2);   // zero S + int8 split + stats

    dim3 gridA(R / BN, R / BM);
    kernelA<<<gridA, 256, A_SMEM>>>();

    kernelB<<<R / 2, 256>>>(out);
}

// round 14
// speedup vs baseline: 1.9671x; 1.9671x over previous
#include <cuda_runtime.h>
#include <cuda_bf16.h>
#include <cstdint>

#define R 4096
#define F 256
#define K 8
#define CMIN 1e-6f
#define CMAX 1e6f
#define C_BIAS 0.5287663729448977f  /* log2(log2(e)) */

#define BM 128
#define BN 128
#define TILE_B 16384               // one 128row x 128B bf16 tile (BK=64)
#define A_SMEM (3 * TILE_B + 1024)

// Scratch (static device globals — no runtime allocation)
__device__ __align__(16) float g_base[(size_t)R * (size_t)R];  // 64 MB
__device__ __align__(16) float g_S[K * R];
__device__ __align__(16) float g_rs[4 * R];     // sx1 | n2x1 | sx2 | n2x2
__device__ __align__(16) float g_kc[5 * K];     // compacted: akt|bkt2|ekc2|hi|nw
__device__ int g_nact;
__device__ __align__(16) __nv_bfloat16 g_x1h[R * F];
__device__ __align__(16) __nv_bfloat16 g_x1l[R * F];
__device__ __align__(16) __nv_bfloat16 g_x2h[R * F];

__device__ __forceinline__ uint32_t smem_u32(const void* p) {
    uint32_t a;
    asm("{ .reg .u64 t; cvta.to.shared.u64 t, %1; cvt.u32.u64 %0, t; }"
        : "=r"(a) : "l"(p));
    return a;
}
__device__ __forceinline__ float ex2f(float x) {
    float y;
    asm("ex2.approx.ftz.f32 %0, %1;" : "=f"(y) : "f"(x));
    return y;
}
__device__ __forceinline__ void ldsm_x4(uint32_t* r, uint32_t addr) {
    asm volatile("ldmatrix.sync.aligned.m8n8.x4.shared.b16 {%0,%1,%2,%3}, [%4];"
                 : "=r"(r[0]), "=r"(r[1]), "=r"(r[2]), "=r"(r[3]) : "r"(addr));
}
__device__ __forceinline__ void mma16816(float* c, const uint32_t* a,
                                         uint32_t b0, uint32_t b1) {
    asm volatile(
        "mma.sync.aligned.m16n8k16.row.col.f32.bf16.bf16.f32 "
        "{%0,%1,%2,%3}, {%4,%5,%6,%7}, {%8,%9}, {%0,%1,%2,%3};"
        : "+f"(c[0]), "+f"(c[1]), "+f"(c[2]), "+f"(c[3])
        : "r"(a[0]), "r"(a[1]), "r"(a[2]), "r"(a[3]), "r"(b0), "r"(b1));
}

// ---------------------------------------------------------------------------
// Per-k constants, compacted to softmax weights > 1e-7 (others contribute
// < 1e-7 relative). arg = dist*ekc2 + C_BIAS; e^kv = ex2(ex2(arg)).
__global__ void params_kernel(const float* __restrict__ sig,
                              const float* __restrict__ mean,
                              const float* __restrict__ sp) {
    if (threadIdx.x == 0) {
        const float L2E = 1.4426950408889634f;
        float w[K];
        float m = -3.4e38f;
        #pragma unroll
        for (int k = 0; k < K; k++) {
            float v = 1.0f / (sp[k] * sp[k]);
            w[k] = v;
            if (v > m) m = v;
        }
        float s = 0.0f;
        #pragma unroll
        for (int k = 0; k < K; k++) { w[k] = __expf(w[k] - m); s += w[k]; }
        float inv_s = 1.0f / s;
        int na = 0;
        for (int k = 0; k < K; k++) {
            float nw = w[k] * inv_s;
            if (nw > 1e-7f) {
                float ekc2 = -L2E / (2.0f * sig[k] * sig[k]);
                float ak   = -2.0f * mean[k];
                float bk   = (float)F * mean[k] * mean[k];
                g_kc[na]         = ak * ekc2;              // akt
                g_kc[K + na]     = bk * ekc2 + C_BIAS;     // bkt2
                g_kc[2 * K + na] = ekc2;
                g_kc[3 * K + na] = CMIN * ekc2 + C_BIAS;   // hi clamp
                g_kc[4 * K + na] = nw;                     // weight
                na++;
            }
        }
        g_nact = na;
    }
}

// ---------------------------------------------------------------------------
// Fused prep: zero g_S; one warp per row. x1 rows: bf16 hi/lo split.
// x2 rows: bf16 hi only. All rows: sum + squared norm.
__global__ void __launch_bounds__(256)
prep_kernel(const float* __restrict__ x1, const float* __restrict__ x2) {
    const int gid = blockIdx.x * blockDim.x + threadIdx.x;
    if (gid < K * R) g_S[gid] = 0.0f;

    const int w    = gid >> 5;
    const int lane = gid & 31;
    const bool is1 = (w < R);
    const int row  = is1 ? w : (w - R);
    const float* x = is1 ? x1 : x2;

    const float* p = x + (size_t)row * F + lane * 8;
    float4 v0 = *(const float4*)p;
    float4 v1 = *(const float4*)(p + 4);
    float vals[8] = {v0.x, v0.y, v0.z, v0.w, v1.x, v1.y, v1.z, v1.w};

    float s = 0.0f, q = 0.0f;
    __nv_bfloat16 hb[8], lb[8];
    #pragma unroll
    for (int e = 0; e < 8; e++) {
        float v = vals[e];
        s += v;
        q = fmaf(v, v, q);
        __nv_bfloat16 h = __float2bfloat16(v);
        hb[e] = h;
        lb[e] = __float2bfloat16(v - __bfloat162float(h));
    }
    if (is1) {
        *(uint4*)(g_x1h + (size_t)row * F + lane * 8) = *(const uint4*)hb;
        *(uint4*)(g_x1l + (size_t)row * F + lane * 8) = *(const uint4*)lb;
    } else {
        *(uint4*)(g_x2h + (size_t)row * F + lane * 8) = *(const uint4*)hb;
    }

    #pragma unroll
    for (int o = 16; o > 0; o >>= 1) {
        s += __shfl_xor_sync(0xFFFFFFFFu, s, o);
        q += __shfl_xor_sync(0xFFFFFFFFu, q, o);
    }
    if (lane == 0) {
        int off = is1 ? 0 : 2 * R;
        g_rs[off + row]     = s;
        g_rs[off + R + row] = q;
    }
}

// ---------------------------------------------------------------------------
// Kernel A: 128x128 tile, asymmetric 2-pass bf16 split-GEMM (h1h2 + l1h2)
// via mma.sync m16n8k16. 8 warps 2(m) x 4(n), 64x32 per warp.
// Epilogue: numerator e^kv storage when nact==1, else base + S accumulation.
__global__ void __launch_bounds__(256, 2)
kernelA() {
    extern __shared__ char dynsmem[];
    __shared__ float skc[5 * K];
    __shared__ int s_na;

    const int tid  = threadIdx.x;
    const int wid  = tid >> 5;
    const int lane = tid & 31;
    const int wm = wid & 1;          // m position -> 64 rows
    const int wn = wid >> 1;         // n position -> 32 cols
    const int ln15 = lane & 15;
    const int hi16 = lane >> 4;
    const int r0 = blockIdx.y * BM;
    const int c0 = blockIdx.x * BN;

    const uint32_t dsb = smem_u32(dynsmem);
    const uint32_t tiles_u = (dsb + 1023u) & ~1023u;
    char* tiles = dynsmem + (tiles_u - dsb);

    if (tid < 5 * K) skc[tid] = g_kc[tid];
    if (tid == 0) s_na = g_nact;

    // loader mapping: 128 rows x 64 bf16 tiles, SW128 swizzle
    const int lrow  = tid >> 1;
    const int lcol0 = (tid & 1) * 32;
    const __nv_bfloat16* pah = g_x1h + (size_t)(r0 + lrow) * F + lcol0;
    const __nv_bfloat16* pal = g_x1l + (size_t)(r0 + lrow) * F + lcol0;
    const __nv_bfloat16* pbh = g_x2h + (size_t)(c0 + lrow) * F + lcol0;

    const uint32_t a_row = (uint32_t)(wm * 64 + ln15) * 128u;
    const uint32_t b_row = (uint32_t)(wn * 32 + ln15) * 128u;
    const uint32_t ah_base = tiles_u + 0 * TILE_B + a_row;
    const uint32_t al_base = tiles_u + 1 * TILE_B + a_row;
    const uint32_t bh_base = tiles_u + 2 * TILE_B + b_row;

    float acc[4][4][4];
    #pragma unroll
    for (int i = 0; i < 4; i++)
        #pragma unroll
        for (int j = 0; j < 4; j++)
            #pragma unroll
            for (int c = 0; c < 4; c++) acc[i][j][c] = 0.0f;

    for (int kc = 0; kc < 4; kc++) {
        const int k0 = kc * 64;
        __syncthreads();
        #pragma unroll
        for (int j = 0; j < 4; j++) {
            uint32_t boff = lrow * 128 + (lcol0 + j * 8) * 2;
            uint32_t sw = boff ^ ((boff >> 3) & 0x70);
            *(uint4*)(tiles + 0 * TILE_B + sw) = *(const uint4*)(pah + k0 + j * 8);
            *(uint4*)(tiles + 1 * TILE_B + sw) = *(const uint4*)(pal + k0 + j * 8);
            *(uint4*)(tiles + 2 * TILE_B + sw) = *(const uint4*)(pbh + k0 + j * 8);
        }
        __syncthreads();

        #pragma unroll
        for (int ks = 0; ks < 4; ks++) {
            const uint32_t q = (uint32_t)(((ks * 2 + hi16) ^ (ln15 & 7)) * 16);
            uint32_t ah[4][4], bh[2][4];
            #pragma unroll
            for (int mf = 0; mf < 4; mf++)
                ldsm_x4(ah[mf], ah_base + q + mf * 2048);
            #pragma unroll
            for (int n2 = 0; n2 < 2; n2++)
                ldsm_x4(bh[n2], bh_base + q + n2 * 2048);

            // hh
            #pragma unroll
            for (int mf = 0; mf < 4; mf++)
                #pragma unroll
                for (int nf = 0; nf < 4; nf++)
                    mma16816(acc[mf][nf], ah[mf],
                             bh[nf >> 1][nf & 1], bh[nf >> 1][(nf & 1) + 2]);
            // lh (A-lo overwrites A-hi registers)
            #pragma unroll
            for (int mf = 0; mf < 4; mf++)
                ldsm_x4(ah[mf], al_base + q + mf * 2048);
            #pragma unroll
            for (int mf = 0; mf < 4; mf++)
                #pragma unroll
                for (int nf = 0; nf < 4; nf++)
                    mma16816(acc[mf][nf], ah[mf],
                             bh[nf >> 1][nf & 1], bh[nf >> 1][(nf & 1) + 2]);
        }
    }

    // ---- epilogue ----
    // elem (mf, nf, half, e): row = r0 + wm*64 + mf*16 + half*8 + lane/4
    //                         col = c0 + wn*32 + nf*8 + (lane&3)*2 + e
    const int rbase = r0 + wm * 64 + (lane >> 2);
    const int cbase = c0 + wn * 32 + (lane & 3) * 2;

    float sx1r8[8], n21r8[8];
    #pragma unroll
    for (int i = 0; i < 8; i++) {
        int row = rbase + (i >> 1) * 16 + (i & 1) * 8;
        sx1r8[i] = g_rs[row];
        n21r8[i] = g_rs[R + row];
    }
    float n22c[8], s2c[8];
    #pragma unroll
    for (int nf = 0; nf < 4; nf++) {
        float2 n2 = *(const float2*)&g_rs[3 * R + cbase + nf * 8];
        float2 s2 = *(const float2*)&g_rs[2 * R + cbase + nf * 8];
        n22c[nf * 2] = n2.x; n22c[nf * 2 + 1] = n2.y;
        s2c[nf * 2]  = s2.x; s2c[nf * 2 + 1]  = s2.y;
    }

    // transform accumulators to base in place
    #pragma unroll
    for (int mf = 0; mf < 4; mf++)
        #pragma unroll
        for (int h = 0; h < 2; h++) {
            float n21 = n21r8[mf * 2 + h];
            #pragma unroll
            for (int nf = 0; nf < 4; nf++) {
                acc[mf][nf][h * 2]     = n21 + n22c[nf * 2]     - 2.0f * acc[mf][nf][h * 2];
                acc[mf][nf][h * 2 + 1] = n21 + n22c[nf * 2 + 1] - 2.0f * acc[mf][nf][h * 2 + 1];
            }
        }

    const int na = s_na;
    if (na == 1) {
        // store numerator e^kv directly; kernelB becomes a row-scale pass
        const float akt  = skc[0];
        const float nakt = -akt;
        const float bkt2 = skc[K];
        const float ekc2 = skc[2 * K];
        const float hi   = skc[3 * K];
        #pragma unroll
        for (int mf = 0; mf < 4; mf++)
            #pragma unroll
            for (int h = 0; h < 2; h++) {
                const float pi = fmaf(sx1r8[mf * 2 + h], akt, bkt2);
                float s = 0.0f;
                #pragma unroll
                for (int nf = 0; nf < 4; nf++)
                    #pragma unroll
                    for (int e = 0; e < 2; e++) {
                        int idx = h * 2 + e;
                        float arg = fmaf(acc[mf][nf][idx], ekc2,
                                         fmaf(s2c[nf * 2 + e], nakt, pi));
                        arg = fminf(arg, hi);
                        float kv = ex2f(ex2f(arg));
                        acc[mf][nf][idx] = kv;
                        s += kv;
                    }
                int row = rbase + mf * 16 + h * 8;
                #pragma unroll
                for (int nf = 0; nf < 4; nf++) {
                    float2 o = {acc[mf][nf][h * 2], acc[mf][nf][h * 2 + 1]};
                    *(float2*)&g_base[(size_t)row * R + cbase + nf * 8] = o;
                }
                s += __shfl_xor_sync(0xFFFFFFFFu, s, 1);
                s += __shfl_xor_sync(0xFFFFFFFFu, s, 2);
                if ((lane & 3) == 0)
                    atomicAdd(&g_S[row], s);
            }
    } else {
        #pragma unroll
        for (int mf = 0; mf < 4; mf++)
            #pragma unroll
            for (int h = 0; h < 2; h++) {
                int row = rbase + mf * 16 + h * 8;
                #pragma unroll
                for (int nf = 0; nf < 4; nf++) {
                    float2 o = {acc[mf][nf][h * 2], acc[mf][nf][h * 2 + 1]};
                    *(float2*)&g_base[(size_t)row * R + cbase + nf * 8] = o;
                }
            }
        for (int kk = 0; kk < na; kk++) {
            const float akt  = skc[kk];
            const float nakt = -akt;
            const float bkt2 = skc[K + kk];
            const float ekc2 = skc[2 * K + kk];
            const float hi   = skc[3 * K + kk];
            #pragma unroll
            for (int mf = 0; mf < 4; mf++)
                #pragma unroll
                for (int h = 0; h < 2; h++) {
                    const float pi = fmaf(sx1r8[mf * 2 + h], akt, bkt2);
                    float s = 0.0f;
                    #pragma unroll
                    for (int nf = 0; nf < 4; nf++)
                        #pragma unroll
                        for (int e = 0; e < 2; e++) {
                            float arg = fmaf(acc[mf][nf][h * 2 + e], ekc2,
                                             fmaf(s2c[nf * 2 + e], nakt, pi));
                            arg = fminf(arg, hi);
                            s += ex2f(ex2f(arg));
                        }
                    s += __shfl_xor_sync(0xFFFFFFFFu, s, 1);
                    s += __shfl_xor_sync(0xFFFFFFFFu, s, 2);
                    if ((lane & 3) == 0)
                        atomicAdd(&g_S[kk * R + rbase + mf * 16 + h * 8], s);
                }
        }
    }
}

// ---------------------------------------------------------------------------
// Kernel B: two rows per block. nact==1: pure row-scale of stored numerators.
// Otherwise recompute numerators from stored base (double-ex2 on MUFU).
__global__ void __launch_bounds__(256)
kernelB(float* __restrict__ out) {
    const int r0 = blockIdx.x * 2;
    __shared__ float sa[K], se[K], shi[K];
    __shared__ float sw0[K], sw1[K], sp0[K], sp1[K];
    __shared__ int s_na;
    if (threadIdx.x == 0) s_na = g_nact;
    if (threadIdx.x < K) {
        int k = threadIdx.x;
        float akt = g_kc[k];
        float nw  = g_kc[4 * K + k];
        float bkt2 = g_kc[K + k];
        sa[k]  = akt;
        se[k]  = g_kc[2 * K + k];
        shi[k] = g_kc[3 * K + k];
        sw0[k] = nw / g_S[k * R + r0];
        sw1[k] = nw / g_S[k * R + r0 + 1];
        sp0[k] = fmaf(g_rs[r0],     akt, bkt2);
        sp1[k] = fmaf(g_rs[r0 + 1], akt, bkt2);
    }
    __syncthreads();

    const int na = s_na;
    const float* brow0 = g_base + (size_t)r0 * R;
    const float* brow1 = g_base + (size_t)(r0 + 1) * R;
    float* orow0 = out + (size_t)r0 * R;
    float* orow1 = out + (size_t)(r0 + 1) * R;

    if (na == 1) {
        const float w0 = sw0[0], w1 = sw1[0];
        #pragma unroll
        for (int it = 0; it < R / (256 * 4); it++) {
            int c = (it * 256 + threadIdx.x) * 4;
            float4 b0 = *(const float4*)(brow0 + c);
            float4 b1 = *(const float4*)(brow1 + c);
            float4 o0 = {b0.x * w0, b0.y * w0, b0.z * w0, b0.w * w0};
            float4 o1 = {b1.x * w1, b1.y * w1, b1.z * w1, b1.w * w1};
            *(float4*)(orow0 + c) = o0;
            *(float4*)(orow1 + c) = o1;
        }
        return;
    }

    #pragma unroll
    for (int it = 0; it < R / (256 * 4); it++) {
        int c = (it * 256 + threadIdx.x) * 4;
        float4 s4  = *(const float4*)(g_rs + 2 * R + c);
        float4 b40 = *(const float4*)(brow0 + c);
        float4 b41 = *(const float4*)(brow1 + c);
        const float* cc  = (const float*)&s4;
        const float* bb0 = (const float*)&b40;
        const float* bb1 = (const float*)&b41;
        float o0[4] = {0.0f, 0.0f, 0.0f, 0.0f};
        float o1[4] = {0.0f, 0.0f, 0.0f, 0.0f};
        for (int kk = 0; kk < na; kk++) {
            const float nakt = -sa[kk];
            const float ekc2 = se[kk];
            const float hi   = shi[kk];
            const float wk0  = sw0[kk];
            const float wk1  = sw1[kk];
            const float pr0  = sp0[kk];
            const float pr1  = sp1[kk];
            #pragma unroll
            for (int j = 0; j < 4; j++) {
                float t = cc[j] * nakt;
                float a0 = fmaf(bb0[j], ekc2, t + pr0);
                float a1 = fmaf(bb1[j], ekc2, t + pr1);
                a0 = fminf(a0, hi);
                a1 = fminf(a1, hi);
                o0[j] = fmaf(ex2f(ex2f(a0)), wk0, o0[j]);
                o1[j] = fmaf(ex2f(ex2f(a1)), wk1, o1[j]);
            }
        }
        float4 ov0 = {o0[0], o0[1], o0[2], o0[3]};
        float4 ov1 = {o1[0], o1[1], o1[2], o1[3]};
        *(float4*)(orow0 + c) = ov0;
        *(float4*)(orow1 + c) = ov1;
    }
}

// ---------------------------------------------------------------------------
extern "C" void kernel_launch(void* const* d_in, const int* in_sizes, int n_in,
                              void* d_out, int out_size) {
    const float* x1   = (const float*)d_in[0];  // [R, F]
    const float* x2   = (const float*)d_in[1];  // [R, F]
    const float* sig  = (const float*)d_in[2];  // [K]
    const float* mean = (const float*)d_in[3];  // [K]
    const float* sp   = (const float*)d_in[4];  // [K]
    float* out = (float*)d_out;                 // [R, R]

    cudaFuncSetAttribute(kernelA, cudaFuncAttributeMaxDynamicSharedMemorySize,
                         A_SMEM);

    params_kernel<<<1, 32>>>(sig, mean, sp);
    prep_kernel<<<(2 * R) / 8, 256>>>(x1, x2);   // zero S + split + stats

    dim3 gridA(R / BN, R / BM);
    kernelA<<<gridA, 256, A_SMEM>>>();

    kernelB<<<R / 2, 256>>>(out);
}

// round 15
// speedup vs baseline: 2.5937x; 1.3185x over previous
#include <cuda_runtime.h>
#include <cuda_bf16.h>
#include <cstdint>

#define R 4096
#define F 256
#define K 8
#define CMIN 1e-6f
#define CMAX 1e6f
#define C_BIAS 0.5287663729448977f  /* log2(log2(e)) */

#define BM 128
#define BN 128
#define TILE_B 16384               // one 128row x 128B bf16 tile (BK=64)
#define A_SMEM (2 * TILE_B + 1024)

// Scratch (static device globals — no runtime allocation)
__device__ __align__(16) float g_base[(size_t)R * (size_t)R];  // 64 MB
__device__ __align__(16) float g_S[K * R];
__device__ __align__(16) float g_rs[4 * R];     // sx1 | n2x1 | sx2 | n2x2
__device__ __align__(16) float g_kc[5 * K];     // compacted: akt|bkt2|ekc2|hi|nw
__device__ int g_nact;
__device__ __align__(16) __nv_bfloat16 g_x1h[R * F];
__device__ __align__(16) __nv_bfloat16 g_x2h[R * F];

__device__ __forceinline__ uint32_t smem_u32(const void* p) {
    uint32_t a;
    asm("{ .reg .u64 t; cvta.to.shared.u64 t, %1; cvt.u32.u64 %0, t; }"
        : "=r"(a) : "l"(p));
    return a;
}
__device__ __forceinline__ float ex2f(float x) {
    float y;
    asm("ex2.approx.ftz.f32 %0, %1;" : "=f"(y) : "f"(x));
    return y;
}
__device__ __forceinline__ void ldsm_x4(uint32_t* r, uint32_t addr) {
    asm volatile("ldmatrix.sync.aligned.m8n8.x4.shared.b16 {%0,%1,%2,%3}, [%4];"
                 : "=r"(r[0]), "=r"(r[1]), "=r"(r[2]), "=r"(r[3]) : "r"(addr));
}
__device__ __forceinline__ void mma16816(float* c, const uint32_t* a,
                                         uint32_t b0, uint32_t b1) {
    asm volatile(
        "mma.sync.aligned.m16n8k16.row.col.f32.bf16.bf16.f32 "
        "{%0,%1,%2,%3}, {%4,%5,%6,%7}, {%8,%9}, {%0,%1,%2,%3};"
        : "+f"(c[0]), "+f"(c[1]), "+f"(c[2]), "+f"(c[3])
        : "r"(a[0]), "r"(a[1]), "r"(a[2]), "r"(a[3]), "r"(b0), "r"(b1));
}

// ---------------------------------------------------------------------------
// Per-k constants, compacted to softmax weights > 1e-7 (others contribute
// < 1e-7 relative). arg = dist*ekc2 + C_BIAS; e^kv = ex2(ex2(arg)).
__global__ void params_kernel(const float* __restrict__ sig,
                              const float* __restrict__ mean,
                              const float* __restrict__ sp) {
    if (threadIdx.x == 0) {
        const float L2E = 1.4426950408889634f;
        float w[K];
        float m = -3.4e38f;
        #pragma unroll
        for (int k = 0; k < K; k++) {
            float v = 1.0f / (sp[k] * sp[k]);
            w[k] = v;
            if (v > m) m = v;
        }
        float s = 0.0f;
        #pragma unroll
        for (int k = 0; k < K; k++) { w[k] = __expf(w[k] - m); s += w[k]; }
        float inv_s = 1.0f / s;
        int na = 0;
        for (int k = 0; k < K; k++) {
            float nw = w[k] * inv_s;
            if (nw > 1e-7f) {
                float ekc2 = -L2E / (2.0f * sig[k] * sig[k]);
                float ak   = -2.0f * mean[k];
                float bk   = (float)F * mean[k] * mean[k];
                g_kc[na]         = ak * ekc2;              // akt
                g_kc[K + na]     = bk * ekc2 + C_BIAS;     // bkt2
                g_kc[2 * K + na] = ekc2;
                g_kc[3 * K + na] = CMIN * ekc2 + C_BIAS;   // hi clamp
                g_kc[4 * K + na] = nw;                     // weight
                na++;
            }
        }
        g_nact = na;
    }
}

// ---------------------------------------------------------------------------
// Fused prep: zero g_S; one warp per row; bf16 round + row sum + sq-norm.
__global__ void __launch_bounds__(256)
prep_kernel(const float* __restrict__ x1, const float* __restrict__ x2) {
    const int gid = blockIdx.x * blockDim.x + threadIdx.x;
    if (gid < K * R) g_S[gid] = 0.0f;

    const int w    = gid >> 5;
    const int lane = gid & 31;
    const bool is1 = (w < R);
    const int row  = is1 ? w : (w - R);
    const float* x = is1 ? x1 : x2;
    __nv_bfloat16* xh = is1 ? g_x1h : g_x2h;

    const float* p = x + (size_t)row * F + lane * 8;
    float4 v0 = *(const float4*)p;
    float4 v1 = *(const float4*)(p + 4);
    float vals[8] = {v0.x, v0.y, v0.z, v0.w, v1.x, v1.y, v1.z, v1.w};

    float s = 0.0f, q = 0.0f;
    __nv_bfloat16 hb[8];
    #pragma unroll
    for (int e = 0; e < 8; e++) {
        float v = vals[e];
        s += v;
        q = fmaf(v, v, q);
        hb[e] = __float2bfloat16(v);
    }
    *(uint4*)(xh + (size_t)row * F + lane * 8) = *(const uint4*)hb;

    #pragma unroll
    for (int o = 16; o > 0; o >>= 1) {
        s += __shfl_xor_sync(0xFFFFFFFFu, s, o);
        q += __shfl_xor_sync(0xFFFFFFFFu, q, o);
    }
    if (lane == 0) {
        int off = is1 ? 0 : 2 * R;
        g_rs[off + row]     = s;
        g_rs[off + R + row] = q;
    }
}

// ---------------------------------------------------------------------------
// Kernel A: 128x128 tile, single-pass bf16 GEMM via mma.sync m16n8k16.
// 8 warps 2(m) x 4(n), 64x32 per warp, fp32 accumulators.
// Epilogue: numerator e^kv storage when nact==1, else base + S accumulation.
__global__ void __launch_bounds__(256, 2)
kernelA() {
    extern __shared__ char dynsmem[];
    __shared__ float skc[5 * K];
    __shared__ int s_na;

    const int tid  = threadIdx.x;
    const int wid  = tid >> 5;
    const int lane = tid & 31;
    const int wm = wid & 1;          // m position -> 64 rows
    const int wn = wid >> 1;         // n position -> 32 cols
    const int ln15 = lane & 15;
    const int hi16 = lane >> 4;
    const int r0 = blockIdx.y * BM;
    const int c0 = blockIdx.x * BN;

    const uint32_t dsb = smem_u32(dynsmem);
    const uint32_t tiles_u = (dsb + 1023u) & ~1023u;
    char* tiles = dynsmem + (tiles_u - dsb);

    if (tid < 5 * K) skc[tid] = g_kc[tid];
    if (tid == 0) s_na = g_nact;

    // loader mapping: 128 rows x 64 bf16 tiles, SW128 swizzle
    const int lrow  = tid >> 1;
    const int lcol0 = (tid & 1) * 32;
    const __nv_bfloat16* pah = g_x1h + (size_t)(r0 + lrow) * F + lcol0;
    const __nv_bfloat16* pbh = g_x2h + (size_t)(c0 + lrow) * F + lcol0;

    const uint32_t a_row = (uint32_t)(wm * 64 + ln15) * 128u;
    const uint32_t b_row = (uint32_t)(wn * 32 + ln15) * 128u;
    const uint32_t ah_base = tiles_u + 0 * TILE_B + a_row;
    const uint32_t bh_base = tiles_u + 1 * TILE_B + b_row;

    float acc[4][4][4];
    #pragma unroll
    for (int i = 0; i < 4; i++)
        #pragma unroll
        for (int j = 0; j < 4; j++)
            #pragma unroll
            for (int c = 0; c < 4; c++) acc[i][j][c] = 0.0f;

    for (int kc = 0; kc < 4; kc++) {
        const int k0 = kc * 64;
        __syncthreads();
        #pragma unroll
        for (int j = 0; j < 4; j++) {
            uint32_t boff = lrow * 128 + (lcol0 + j * 8) * 2;
            uint32_t sw = boff ^ ((boff >> 3) & 0x70);
            *(uint4*)(tiles + 0 * TILE_B + sw) = *(const uint4*)(pah + k0 + j * 8);
            *(uint4*)(tiles + 1 * TILE_B + sw) = *(const uint4*)(pbh + k0 + j * 8);
        }
        __syncthreads();

        #pragma unroll
        for (int ks = 0; ks < 4; ks++) {
            const uint32_t q = (uint32_t)(((ks * 2 + hi16) ^ (ln15 & 7)) * 16);
            uint32_t ah[4][4], bh[2][4];
            #pragma unroll
            for (int mf = 0; mf < 4; mf++)
                ldsm_x4(ah[mf], ah_base + q + mf * 2048);
            #pragma unroll
            for (int n2 = 0; n2 < 2; n2++)
                ldsm_x4(bh[n2], bh_base + q + n2 * 2048);

            #pragma unroll
            for (int mf = 0; mf < 4; mf++)
                #pragma unroll
                for (int nf = 0; nf < 4; nf++)
                    mma16816(acc[mf][nf], ah[mf],
                             bh[nf >> 1][nf & 1], bh[nf >> 1][(nf & 1) + 2]);
        }
    }

    // ---- epilogue ----
    // elem (mf, nf, half, e): row = r0 + wm*64 + mf*16 + half*8 + lane/4
    //                         col = c0 + wn*32 + nf*8 + (lane&3)*2 + e
    const int rbase = r0 + wm * 64 + (lane >> 2);
    const int cbase = c0 + wn * 32 + (lane & 3) * 2;

    float sx1r8[8], n21r8[8];
    #pragma unroll
    for (int i = 0; i < 8; i++) {
        int row = rbase + (i >> 1) * 16 + (i & 1) * 8;
        sx1r8[i] = g_rs[row];
        n21r8[i] = g_rs[R + row];
    }
    float n22c[8], s2c[8];
    #pragma unroll
    for (int nf = 0; nf < 4; nf++) {
        float2 n2 = *(const float2*)&g_rs[3 * R + cbase + nf * 8];
        float2 s2 = *(const float2*)&g_rs[2 * R + cbase + nf * 8];
        n22c[nf * 2] = n2.x; n22c[nf * 2 + 1] = n2.y;
        s2c[nf * 2]  = s2.x; s2c[nf * 2 + 1]  = s2.y;
    }

    // transform accumulators to base in place
    #pragma unroll
    for (int mf = 0; mf < 4; mf++)
        #pragma unroll
        for (int h = 0; h < 2; h++) {
            float n21 = n21r8[mf * 2 + h];
            #pragma unroll
            for (int nf = 0; nf < 4; nf++) {
                acc[mf][nf][h * 2]     = n21 + n22c[nf * 2]     - 2.0f * acc[mf][nf][h * 2];
                acc[mf][nf][h * 2 + 1] = n21 + n22c[nf * 2 + 1] - 2.0f * acc[mf][nf][h * 2 + 1];
            }
        }

    const int na = s_na;
    if (na == 1) {
        // store numerator e^kv directly; kernelB becomes a row-scale pass
        const float akt  = skc[0];
        const float nakt = -akt;
        const float bkt2 = skc[K];
        const float ekc2 = skc[2 * K];
        const float hi   = skc[3 * K];
        #pragma unroll
        for (int mf = 0; mf < 4; mf++)
            #pragma unroll
            for (int h = 0; h < 2; h++) {
                const float pi = fmaf(sx1r8[mf * 2 + h], akt, bkt2);
                float s = 0.0f;
                #pragma unroll
                for (int nf = 0; nf < 4; nf++)
                    #pragma unroll
                    for (int e = 0; e < 2; e++) {
                        int idx = h * 2 + e;
                        float arg = fmaf(acc[mf][nf][idx], ekc2,
                                         fmaf(s2c[nf * 2 + e], nakt, pi));
                        arg = fminf(arg, hi);
                        float kv = ex2f(ex2f(arg));
                        acc[mf][nf][idx] = kv;
                        s += kv;
                    }
                int row = rbase + mf * 16 + h * 8;
                #pragma unroll
                for (int nf = 0; nf < 4; nf++) {
                    float2 o = {acc[mf][nf][h * 2], acc[mf][nf][h * 2 + 1]};
                    *(float2*)&g_base[(size_t)row * R + cbase + nf * 8] = o;
                }
                s += __shfl_xor_sync(0xFFFFFFFFu, s, 1);
                s += __shfl_xor_sync(0xFFFFFFFFu, s, 2);
                if ((lane & 3) == 0)
                    atomicAdd(&g_S[row], s);
            }
    } else {
        #pragma unroll
        for (int mf = 0; mf < 4; mf++)
            #pragma unroll
            for (int h = 0; h < 2; h++) {
                int row = rbase + mf * 16 + h * 8;
                #pragma unroll
                for (int nf = 0; nf < 4; nf++) {
                    float2 o = {acc[mf][nf][h * 2], acc[mf][nf][h * 2 + 1]};
                    *(float2*)&g_base[(size_t)row * R + cbase + nf * 8] = o;
                }
            }
        for (int kk = 0; kk < na; kk++) {
            const float akt  = skc[kk];
            const float nakt = -akt;
            const float bkt2 = skc[K + kk];
            const float ekc2 = skc[2 * K + kk];
            const float hi   = skc[3 * K + kk];
            #pragma unroll
            for (int mf = 0; mf < 4; mf++)
                #pragma unroll
                for (int h = 0; h < 2; h++) {
                    const float pi = fmaf(sx1r8[mf * 2 + h], akt, bkt2);
                    float s = 0.0f;
                    #pragma unroll
                    for (int nf = 0; nf < 4; nf++)
                        #pragma unroll
                        for (int e = 0; e < 2; e++) {
                            float arg = fmaf(acc[mf][nf][h * 2 + e], ekc2,
                                             fmaf(s2c[nf * 2 + e], nakt, pi));
                            arg = fminf(arg, hi);
                            s += ex2f(ex2f(arg));
                        }
                    s += __shfl_xor_sync(0xFFFFFFFFu, s, 1);
                    s += __shfl_xor_sync(0xFFFFFFFFu, s, 2);
                    if ((lane & 3) == 0)
                        atomicAdd(&g_S[kk * R + rbase + mf * 16 + h * 8], s);
                }
        }
    }
}

// ---------------------------------------------------------------------------
// Kernel B: two rows per block. nact==1: pure row-scale of stored numerators.
// Otherwise recompute numerators from stored base (double-ex2 on MUFU).
__global__ void __launch_bounds__(256)
kernelB(float* __restrict__ out) {
    const int r0 = blockIdx.x * 2;
    __shared__ float sa[K], se[K], shi[K];
    __shared__ float sw0[K], sw1[K], sp0[K], sp1[K];
    __shared__ int s_na;
    if (threadIdx.x == 0) s_na = g_nact;
    if (threadIdx.x < K) {
        int k = threadIdx.x;
        float akt = g_kc[k];
        float nw  = g_kc[4 * K + k];
        float bkt2 = g_kc[K + k];
        sa[k]  = akt;
        se[k]  = g_kc[2 * K + k];
        shi[k] = g_kc[3 * K + k];
        sw0[k] = nw / g_S[k * R + r0];
        sw1[k] = nw / g_S[k * R + r0 + 1];
        sp0[k] = fmaf(g_rs[r0],     akt, bkt2);
        sp1[k] = fmaf(g_rs[r0 + 1], akt, bkt2);
    }
    __syncthreads();

    const int na = s_na;
    const float* brow0 = g_base + (size_t)r0 * R;
    const float* brow1 = g_base + (size_t)(r0 + 1) * R;
    float* orow0 = out + (size_t)r0 * R;
    float* orow1 = out + (size_t)(r0 + 1) * R;

    if (na == 1) {
        const float w0 = sw0[0], w1 = sw1[0];
        #pragma unroll
        for (int it = 0; it < R / (256 * 4); it++) {
            int c = (it * 256 + threadIdx.x) * 4;
            float4 b0 = *(const float4*)(brow0 + c);
            float4 b1 = *(const float4*)(brow1 + c);
            float4 o0 = {b0.x * w0, b0.y * w0, b0.z * w0, b0.w * w0};
            float4 o1 = {b1.x * w1, b1.y * w1, b1.z * w1, b1.w * w1};
            *(float4*)(orow0 + c) = o0;
            *(float4*)(orow1 + c) = o1;
        }
        return;
    }

    #pragma unroll
    for (int it = 0; it < R / (256 * 4); it++) {
        int c = (it * 256 + threadIdx.x) * 4;
        float4 s4  = *(const float4*)(g_rs + 2 * R + c);
        float4 b40 = *(const float4*)(brow0 + c);
        float4 b41 = *(const float4*)(brow1 + c);
        const float* cc  = (const float*)&s4;
        const float* bb0 = (const float*)&b40;
        const float* bb1 = (const float*)&b41;
        float o0[4] = {0.0f, 0.0f, 0.0f, 0.0f};
        float o1[4] = {0.0f, 0.0f, 0.0f, 0.0f};
        for (int kk = 0; kk < na; kk++) {
            const float nakt = -sa[kk];
            const float ekc2 = se[kk];
            const float hi   = shi[kk];
            const float wk0  = sw0[kk];
            const float wk1  = sw1[kk];
            const float pr0  = sp0[kk];
            const float pr1  = sp1[kk];
            #pragma unroll
            for (int j = 0; j < 4; j++) {
                float t = cc[j] * nakt;
                float a0 = fmaf(bb0[j], ekc2, t + pr0);
                float a1 = fmaf(bb1[j], ekc2, t + pr1);
                a0 = fminf(a0, hi);
                a1 = fminf(a1, hi);
                o0[j] = fmaf(ex2f(ex2f(a0)), wk0, o0[j]);
                o1[j] = fmaf(ex2f(ex2f(a1)), wk1, o1[j]);
            }
        }
        float4 ov0 = {o0[0], o0[1], o0[2], o0[3]};
        float4 ov1 = {o1[0], o1[1], o1[2], o1[3]};
        *(float4*)(orow0 + c) = ov0;
        *(float4*)(orow1 + c) = ov1;
    }
}

// ---------------------------------------------------------------------------
extern "C" void kernel_launch(void* const* d_in, const int* in_sizes, int n_in,
                              void* d_out, int out_size) {
    const float* x1   = (const float*)d_in[0];  // [R, F]
    const float* x2   = (const float*)d_in[1];  // [R, F]
    const float* sig  = (const float*)d_in[2];  // [K]
    const float* mean = (const float*)d_in[3];  // [K]
    const float* sp   = (const float*)d_in[4];  // [K]
    float* out = (float*)d_out;                 // [R, R]

    cudaFuncSetAttribute(kernelA, cudaFuncAttributeMaxDynamicSharedMemorySize,
                         A_SMEM);

    params_kernel<<<1, 32>>>(sig, mean, sp);
    prep_kernel<<<(2 * R) / 8, 256>>>(x1, x2);   // zero S + bf16 round + stats

    dim3 gridA(R / BN, R / BM);
    kernelA<<<gridA, 256, A_SMEM>>>();

    kernelB<<<R / 2, 256>>>(out);
}

// round 16
// speedup vs baseline: 2.9707x; 1.1454x over previous
#include <cuda_runtime.h>
#include <cuda_bf16.h>
#include <cuda_fp16.h>
#include <cstdint>

#define R 4096
#define F 256
#define K 8
#define CMIN 1e-6f
#define CMAX 1e6f
#define C_BIAS 0.5287663729448977f  /* log2(log2(e)) */

#define BM 128
#define BN 128
#define TILE_B 16384               // one 128row x 128B bf16 tile (BK=64)
#define A_SMEM (4 * TILE_B + 1024) // double-buffered A+B tiles

// Scratch (static device globals — no runtime allocation)
__device__ __align__(16) float g_base[(size_t)R * (size_t)R];  // na>1 path
__device__ __align__(16) __half g_num[(size_t)R * (size_t)R];  // na==1 path
__device__ __align__(16) float g_S[K * R];
__device__ __align__(16) float g_rs[4 * R];     // sx1 | n2x1 | sx2 | n2x2
__device__ __align__(16) float g_kc[5 * K];     // compacted: akt|bkt2|ekc2|hi|nw
__device__ int g_nact;
__device__ __align__(16) __nv_bfloat16 g_x1h[R * F];
__device__ __align__(16) __nv_bfloat16 g_x2h[R * F];

__device__ __forceinline__ uint32_t smem_u32(const void* p) {
    uint32_t a;
    asm("{ .reg .u64 t; cvta.to.shared.u64 t, %1; cvt.u32.u64 %0, t; }"
        : "=r"(a) : "l"(p));
    return a;
}
__device__ __forceinline__ float ex2f(float x) {
    float y;
    asm("ex2.approx.ftz.f32 %0, %1;" : "=f"(y) : "f"(x));
    return y;
}
__device__ __forceinline__ void ldsm_x4(uint32_t* r, uint32_t addr) {
    asm volatile("ldmatrix.sync.aligned.m8n8.x4.shared.b16 {%0,%1,%2,%3}, [%4];"
                 : "=r"(r[0]), "=r"(r[1]), "=r"(r[2]), "=r"(r[3]) : "r"(addr));
}
__device__ __forceinline__ void mma16816(float* c, const uint32_t* a,
                                         uint32_t b0, uint32_t b1) {
    asm volatile(
        "mma.sync.aligned.m16n8k16.row.col.f32.bf16.bf16.f32 "
        "{%0,%1,%2,%3}, {%4,%5,%6,%7}, {%8,%9}, {%0,%1,%2,%3};"
        : "+f"(c[0]), "+f"(c[1]), "+f"(c[2]), "+f"(c[3])
        : "r"(a[0]), "r"(a[1]), "r"(a[2]), "r"(a[3]), "r"(b0), "r"(b1));
}
__device__ __forceinline__ void cp16(uint32_t dst, const void* src) {
    asm volatile("cp.async.cg.shared.global [%0], [%1], 16;"
                 :: "r"(dst), "l"(src) : "memory");
}
#define CP_COMMIT() asm volatile("cp.async.commit_group;" ::: "memory")
#define CP_WAIT(n)  asm volatile("cp.async.wait_group %0;" :: "n"(n) : "memory")

// ---------------------------------------------------------------------------
// Fused prep: block 0 thread 0 computes the compacted per-k constants
// (softmax weights > 1e-7 kept). All blocks: zero g_S; one warp per row
// computes bf16 rounding + row sum + squared norm.
__global__ void __launch_bounds__(256)
prep_kernel(const float* __restrict__ x1, const float* __restrict__ x2,
            const float* __restrict__ sig, const float* __restrict__ mean,
            const float* __restrict__ sp) {
    const int gid = blockIdx.x * blockDim.x + threadIdx.x;
    if (gid == 0) {
        const float L2E = 1.4426950408889634f;
        float w[K];
        float m = -3.4e38f;
        #pragma unroll
        for (int k = 0; k < K; k++) {
            float v = 1.0f / (sp[k] * sp[k]);
            w[k] = v;
            if (v > m) m = v;
        }
        float s = 0.0f;
        #pragma unroll
        for (int k = 0; k < K; k++) { w[k] = __expf(w[k] - m); s += w[k]; }
        float inv_s = 1.0f / s;
        int na = 0;
        for (int k = 0; k < K; k++) {
            float nw = w[k] * inv_s;
            if (nw > 1e-7f) {
                float ekc2 = -L2E / (2.0f * sig[k] * sig[k]);
                float ak   = -2.0f * mean[k];
                float bk   = (float)F * mean[k] * mean[k];
                g_kc[na]         = ak * ekc2;              // akt
                g_kc[K + na]     = bk * ekc2 + C_BIAS;     // bkt2
                g_kc[2 * K + na] = ekc2;
                g_kc[3 * K + na] = CMIN * ekc2 + C_BIAS;   // hi clamp
                g_kc[4 * K + na] = nw;                     // weight
                na++;
            }
        }
        g_nact = na;
    }
    if (gid < K * R) g_S[gid] = 0.0f;

    const int w    = gid >> 5;
    const int lane = gid & 31;
    const bool is1 = (w < R);
    const int row  = is1 ? w : (w - R);
    const float* x = is1 ? x1 : x2;
    __nv_bfloat16* xh = is1 ? g_x1h : g_x2h;

    const float* p = x + (size_t)row * F + lane * 8;
    float4 v0 = *(const float4*)p;
    float4 v1 = *(const float4*)(p + 4);
    float vals[8] = {v0.x, v0.y, v0.z, v0.w, v1.x, v1.y, v1.z, v1.w};

    float s = 0.0f, q = 0.0f;
    __nv_bfloat16 hb[8];
    #pragma unroll
    for (int e = 0; e < 8; e++) {
        float v = vals[e];
        s += v;
        q = fmaf(v, v, q);
        hb[e] = __float2bfloat16(v);
    }
    *(uint4*)(xh + (size_t)row * F + lane * 8) = *(const uint4*)hb;

    #pragma unroll
    for (int o = 16; o > 0; o >>= 1) {
        s += __shfl_xor_sync(0xFFFFFFFFu, s, o);
        q += __shfl_xor_sync(0xFFFFFFFFu, q, o);
    }
    if (lane == 0) {
        int off = is1 ? 0 : 2 * R;
        g_rs[off + row]     = s;
        g_rs[off + R + row] = q;
    }
}

// ---------------------------------------------------------------------------
// Kernel A: 128x128 tile, single-pass bf16 GEMM via mma.sync m16n8k16,
// cp.async double-buffered k-loop (2-deep). 8 warps 2(m) x 4(n).
// Epilogue: fp16 numerator storage when nact==1, else fp32 base + S.
__global__ void __launch_bounds__(256, 2)
kernelA() {
    extern __shared__ char dynsmem[];
    __shared__ float skc[5 * K];
    __shared__ int s_na;

    const int tid  = threadIdx.x;
    const int wid  = tid >> 5;
    const int lane = tid & 31;
    const int wm = wid & 1;          // m position -> 64 rows
    const int wn = wid >> 1;         // n position -> 32 cols
    const int ln15 = lane & 15;
    const int hi16 = lane >> 4;
    const int r0 = blockIdx.y * BM;
    const int c0 = blockIdx.x * BN;

    const uint32_t dsb = smem_u32(dynsmem);
    const uint32_t tiles_u = (dsb + 1023u) & ~1023u;

    if (tid < 5 * K) skc[tid] = g_kc[tid];
    if (tid == 0) s_na = g_nact;

    // loader mapping: 128 rows x 64 bf16 tiles, SW128 swizzle
    const int lrow  = tid >> 1;
    const int lcol0 = (tid & 1) * 32;
    const __nv_bfloat16* pah = g_x1h + (size_t)(r0 + lrow) * F + lcol0;
    const __nv_bfloat16* pbh = g_x2h + (size_t)(c0 + lrow) * F + lcol0;

    // per-thread swizzled destination offsets (4 x 16B per tile)
    uint32_t swo[4];
    #pragma unroll
    for (int j = 0; j < 4; j++) {
        uint32_t boff = lrow * 128 + (lcol0 + j * 8) * 2;
        swo[j] = boff ^ ((boff >> 3) & 0x70);
    }

    // buf b: A at tiles_u + b*2*TILE_B, B at +TILE_B
    const uint32_t a_row = (uint32_t)(wm * 64 + ln15) * 128u;
    const uint32_t b_row = (uint32_t)(wn * 32 + ln15) * 128u;

    float acc[4][4][4];
    #pragma unroll
    for (int i = 0; i < 4; i++)
        #pragma unroll
        for (int j = 0; j < 4; j++)
            #pragma unroll
            for (int c = 0; c < 4; c++) acc[i][j][c] = 0.0f;

    // prologue: prefetch chunks 0 and 1
    #pragma unroll
    for (int pc = 0; pc < 2; pc++) {
        const uint32_t ab = tiles_u + pc * 2 * TILE_B;
        const int k0 = pc * 64;
        #pragma unroll
        for (int j = 0; j < 4; j++) {
            cp16(ab + swo[j], pah + k0 + j * 8);
            cp16(ab + TILE_B + swo[j], pbh + k0 + j * 8);
        }
        CP_COMMIT();
    }

    for (int kc = 0; kc < 4; kc++) {
        if (kc < 2) { CP_WAIT(1); } else { CP_WAIT(0); }
        __syncthreads();

        const uint32_t bufo = (uint32_t)(kc & 1) * 2 * TILE_B;
        const uint32_t ah_base = tiles_u + bufo + a_row;
        const uint32_t bh_base = tiles_u + bufo + TILE_B + b_row;

        #pragma unroll
        for (int ks = 0; ks < 4; ks++) {
            const uint32_t q = (uint32_t)(((ks * 2 + hi16) ^ (ln15 & 7)) * 16);
            uint32_t ah[4][4], bh[2][4];
            #pragma unroll
            for (int mf = 0; mf < 4; mf++)
                ldsm_x4(ah[mf], ah_base + q + mf * 2048);
            #pragma unroll
            for (int n2 = 0; n2 < 2; n2++)
                ldsm_x4(bh[n2], bh_base + q + n2 * 2048);

            #pragma unroll
            for (int mf = 0; mf < 4; mf++)
                #pragma unroll
                for (int nf = 0; nf < 4; nf++)
                    mma16816(acc[mf][nf], ah[mf],
                             bh[nf >> 1][nf & 1], bh[nf >> 1][(nf & 1) + 2]);
        }
        __syncthreads();   // all warps done reading this buffer

        if (kc + 2 < 4) {  // prefetch chunk kc+2 into the buffer just freed
            const uint32_t ab = tiles_u + (uint32_t)(kc & 1) * 2 * TILE_B;
            const int k0 = (kc + 2) * 64;
            #pragma unroll
            for (int j = 0; j < 4; j++) {
                cp16(ab + swo[j], pah + k0 + j * 8);
                cp16(ab + TILE_B + swo[j], pbh + k0 + j * 8);
            }
            CP_COMMIT();
        }
    }

    // ---- epilogue ----
    // elem (mf, nf, half, e): row = r0 + wm*64 + mf*16 + half*8 + lane/4
    //                         col = c0 + wn*32 + nf*8 + (lane&3)*2 + e
    const int rbase = r0 + wm * 64 + (lane >> 2);
    const int cbase = c0 + wn * 32 + (lane & 3) * 2;

    float sx1r8[8], n21r8[8];
    #pragma unroll
    for (int i = 0; i < 8; i++) {
        int row = rbase + (i >> 1) * 16 + (i & 1) * 8;
        sx1r8[i] = g_rs[row];
        n21r8[i] = g_rs[R + row];
    }
    float n22c[8], s2c[8];
    #pragma unroll
    for (int nf = 0; nf < 4; nf++) {
        float2 n2 = *(const float2*)&g_rs[3 * R + cbase + nf * 8];
        float2 s2 = *(const float2*)&g_rs[2 * R + cbase + nf * 8];
        n22c[nf * 2] = n2.x; n22c[nf * 2 + 1] = n2.y;
        s2c[nf * 2]  = s2.x; s2c[nf * 2 + 1]  = s2.y;
    }

    // transform accumulators to base in place
    #pragma unroll
    for (int mf = 0; mf < 4; mf++)
        #pragma unroll
        for (int h = 0; h < 2; h++) {
            float n21 = n21r8[mf * 2 + h];
            #pragma unroll
            for (int nf = 0; nf < 4; nf++) {
                acc[mf][nf][h * 2]     = n21 + n22c[nf * 2]     - 2.0f * acc[mf][nf][h * 2];
                acc[mf][nf][h * 2 + 1] = n21 + n22c[nf * 2 + 1] - 2.0f * acc[mf][nf][h * 2 + 1];
            }
        }

    const int na = s_na;
    if (na == 1) {
        // store numerators e^kv as fp16; kernelB becomes a row-scale pass
        const float akt  = skc[0];
        const float nakt = -akt;
        const float bkt2 = skc[K];
        const float ekc2 = skc[2 * K];
        const float hi   = skc[3 * K];
        #pragma unroll
        for (int mf = 0; mf < 4; mf++)
            #pragma unroll
            for (int h = 0; h < 2; h++) {
                const float pi = fmaf(sx1r8[mf * 2 + h], akt, bkt2);
                float s = 0.0f;
                #pragma unroll
                for (int nf = 0; nf < 4; nf++)
                    #pragma unroll
                    for (int e = 0; e < 2; e++) {
                        int idx = h * 2 + e;
                        float arg = fmaf(acc[mf][nf][idx], ekc2,
                                         fmaf(s2c[nf * 2 + e], nakt, pi));
                        arg = fminf(arg, hi);
                        float kv = ex2f(ex2f(arg));
                        acc[mf][nf][idx] = kv;
                        s += kv;
                    }
                int row = rbase + mf * 16 + h * 8;
                __half* np = g_num + (size_t)row * R + cbase;
                #pragma unroll
                for (int nf = 0; nf < 4; nf++) {
                    __half2 hv = __floats2half2_rn(acc[mf][nf][h * 2],
                                                   acc[mf][nf][h * 2 + 1]);
                    *(__half2*)(np + nf * 8) = hv;
                }
                s += __shfl_xor_sync(0xFFFFFFFFu, s, 1);
                s += __shfl_xor_sync(0xFFFFFFFFu, s, 2);
                if ((lane & 3) == 0)
                    atomicAdd(&g_S[row], s);
            }
    } else {
        #pragma unroll
        for (int mf = 0; mf < 4; mf++)
            #pragma unroll
            for (int h = 0; h < 2; h++) {
                int row = rbase + mf * 16 + h * 8;
                #pragma unroll
                for (int nf = 0; nf < 4; nf++) {
                    float2 o = {acc[mf][nf][h * 2], acc[mf][nf][h * 2 + 1]};
                    *(float2*)&g_base[(size_t)row * R + cbase + nf * 8] = o;
                }
            }
        for (int kk = 0; kk < na; kk++) {
            const float akt  = skc[kk];
            const float nakt = -akt;
            const float bkt2 = skc[K + kk];
            const float ekc2 = skc[2 * K + kk];
            const float hi   = skc[3 * K + kk];
            #pragma unroll
            for (int mf = 0; mf < 4; mf++)
                #pragma unroll
                for (int h = 0; h < 2; h++) {
                    const float pi = fmaf(sx1r8[mf * 2 + h], akt, bkt2);
                    float s = 0.0f;
                    #pragma unroll
                    for (int nf = 0; nf < 4; nf++)
                        #pragma unroll
                        for (int e = 0; e < 2; e++) {
                            float arg = fmaf(acc[mf][nf][h * 2 + e], ekc2,
                                             fmaf(s2c[nf * 2 + e], nakt, pi));
                            arg = fminf(arg, hi);
                            s += ex2f(ex2f(arg));
                        }
                    s += __shfl_xor_sync(0xFFFFFFFFu, s, 1);
                    s += __shfl_xor_sync(0xFFFFFFFFu, s, 2);
                    if ((lane & 3) == 0)
                        atomicAdd(&g_S[kk * R + rbase + mf * 16 + h * 8], s);
                }
        }
    }
}

// ---------------------------------------------------------------------------
// Kernel B: two rows per block. nact==1: row-scale of fp16 numerators.
// Otherwise recompute numerators from fp32 base (double-ex2 on MUFU).
__global__ void __launch_bounds__(256)
kernelB(float* __restrict__ out) {
    const int r0 = blockIdx.x * 2;
    __shared__ float sa[K], se[K], shi[K];
    __shared__ float sw0[K], sw1[K], sp0[K], sp1[K];
    __shared__ int s_na;
    if (threadIdx.x == 0) s_na = g_nact;
    if (threadIdx.x < K) {
        int k = threadIdx.x;
        float akt = g_kc[k];
        float nw  = g_kc[4 * K + k];
        float bkt2 = g_kc[K + k];
        sa[k]  = akt;
        se[k]  = g_kc[2 * K + k];
        shi[k] = g_kc[3 * K + k];
        sw0[k] = nw / g_S[k * R + r0];
        sw1[k] = nw / g_S[k * R + r0 + 1];
        sp0[k] = fmaf(g_rs[r0],     akt, bkt2);
        sp1[k] = fmaf(g_rs[r0 + 1], akt, bkt2);
    }
    __syncthreads();

    const int na = s_na;
    float* orow0 = out + (size_t)r0 * R;
    float* orow1 = out + (size_t)(r0 + 1) * R;

    if (na == 1) {
        const float w0 = sw0[0], w1 = sw1[0];
        const __half* nrow0 = g_num + (size_t)r0 * R;
        const __half* nrow1 = g_num + (size_t)(r0 + 1) * R;
        #pragma unroll
        for (int it = 0; it < R / (256 * 8); it++) {
            int c = (it * 256 + threadIdx.x) * 8;
            uint4 h0 = *(const uint4*)(nrow0 + c);
            uint4 h1 = *(const uint4*)(nrow1 + c);
            const __half2* p0 = (const __half2*)&h0;
            const __half2* p1 = (const __half2*)&h1;
            float o0[8], o1[8];
            #pragma unroll
            for (int q = 0; q < 4; q++) {
                float2 f0 = __half22float2(p0[q]);
                float2 f1 = __half22float2(p1[q]);
                o0[q * 2] = f0.x * w0; o0[q * 2 + 1] = f0.y * w0;
                o1[q * 2] = f1.x * w1; o1[q * 2 + 1] = f1.y * w1;
            }
            *(float4*)(orow0 + c)     = *(float4*)&o0[0];
            *(float4*)(orow0 + c + 4) = *(float4*)&o0[4];
            *(float4*)(orow1 + c)     = *(float4*)&o1[0];
            *(float4*)(orow1 + c + 4) = *(float4*)&o1[4];
        }
        return;
    }

    const float* brow0 = g_base + (size_t)r0 * R;
    const float* brow1 = g_base + (size_t)(r0 + 1) * R;
    #pragma unroll
    for (int it = 0; it < R / (256 * 4); it++) {
        int c = (it * 256 + threadIdx.x) * 4;
        float4 s4  = *(const float4*)(g_rs + 2 * R + c);
        float4 b40 = *(const float4*)(brow0 + c);
        float4 b41 = *(const float4*)(brow1 + c);
        const float* cc  = (const float*)&s4;
        const float* bb0 = (const float*)&b40;
        const float* bb1 = (const float*)&b41;
        float o0[4] = {0.0f, 0.0f, 0.0f, 0.0f};
        float o1[4] = {0.0f, 0.0f, 0.0f, 0.0f};
        for (int kk = 0; kk < na; kk++) {
            const float nakt = -sa[kk];
            const float ekc2 = se[kk];
            const float hi   = shi[kk];
            const float wk0  = sw0[kk];
            const float wk1  = sw1[kk];
            const float pr0  = sp0[kk];
            const float pr1  = sp1[kk];
            #pragma unroll
            for (int j = 0; j < 4; j++) {
                float t = cc[j] * nakt;
                float a0 = fmaf(bb0[j], ekc2, t + pr0);
                float a1 = fmaf(bb1[j], ekc2, t + pr1);
                a0 = fminf(a0, hi);
                a1 = fminf(a1, hi);
                o0[j] = fmaf(ex2f(ex2f(a0)), wk0, o0[j]);
                o1[j] = fmaf(ex2f(ex2f(a1)), wk1, o1[j]);
            }
        }
        float4 ov0 = {o0[0], o0[1], o0[2], o0[3]};
        float4 ov1 = {o1[0], o1[1], o1[2], o1[3]};
        *(float4*)(orow0 + c) = ov0;
        *(float4*)(orow1 + c) = ov1;
    }
}

// ---------------------------------------------------------------------------
extern "C" void kernel_launch(void* const* d_in, const int* in_sizes, int n_in,
                              void* d_out, int out_size) {
    const float* x1   = (const float*)d_in[0];  // [R, F]
    const float* x2   = (const float*)d_in[1];  // [R, F]
    const float* sig  = (const float*)d_in[2];  // [K]
    const float* mean = (const float*)d_in[3];  // [K]
    const float* sp   = (const float*)d_in[4];  // [K]
    float* out = (float*)d_out;                 // [R, R]

    cudaFuncSetAttribute(kernelA, cudaFuncAttributeMaxDynamicSharedMemorySize,
                         A_SMEM);

    prep_kernel<<<(2 * R) / 8, 256>>>(x1, x2, sig, mean, sp);

    dim3 gridA(R / BN, R / BM);
    kernelA<<<gridA, 256, A_SMEM>>>();

    kernelB<<<R / 2, 256>>>(out);
}